// round 2
// baseline (speedup 1.0000x reference)
#include <cuda_runtime.h>
#include <cuda_bf16.h>
#include <math.h>

#define BB 2048
#define LL 50
#define DD 128
#define VO 50001
#define BLr (BB*LL)          // 102400 rows

// ---------------- scratch (device globals; no allocation allowed) -------------
__device__ float g_x[(size_t)BLr*DD];        // emb[seq]*mask
__device__ float g_gi[(size_t)BLr*3*DD];     // GRU input gates (precomputed)
__device__ float g_h[(size_t)BB*DD];         // running hidden
__device__ float g_hseq[(size_t)BLr*DD];     // GRU outputs
__device__ float g_hpos[(size_t)BLr*DD];     // hseq + pos
__device__ float g_qkv[(size_t)BLr*3*DD];
__device__ float g_attno[(size_t)BLr*DD];    // attention out (pre out_proj)
__device__ float g_oproj[(size_t)BLr*DD];    // out_proj result
__device__ float g_h1[(size_t)BLr*DD];
__device__ float g_ff[(size_t)BLr*4*DD];
__device__ float g_ff2[(size_t)BLr*DD];
__device__ float g_hattn[(size_t)BLr*DD];
__device__ float g_short[(size_t)BB*DD];
__device__ float g_ehat[(size_t)BB*DD];
__device__ float g_WT[(size_t)DD*3*DD];      // Whh transposed: WT[k][c], c in [0,384)

// ---------------- small elementwise kernels ----------------
__global__ void zero_kernel(float* p, int n) {
    int i = blockIdx.x*blockDim.x + threadIdx.x;
    if (i < n) p[i] = 0.f;
}

__global__ void embed_kernel(const int* __restrict__ seq, const float* __restrict__ emb,
                             float* __restrict__ x) {
    int idx = blockIdx.x*blockDim.x + threadIdx.x;
    if (idx >= BLr*DD) return;
    int bl = idx >> 7; int d = idx & 127;
    int s = seq[bl];
    x[idx] = (s > 0) ? emb[(size_t)s*DD + d] : 0.f;
}

__global__ void addpos_kernel(const float* __restrict__ hseq, const float* __restrict__ pos,
                              float* __restrict__ hpos) {
    int idx = blockIdx.x*blockDim.x + threadIdx.x;
    if (idx >= BLr*DD) return;
    int d = idx & 127;
    int l = (idx >> 7) % LL;
    hpos[idx] = hseq[idx] + pos[l*DD + d];
}

__global__ void transpose_whh(const float* __restrict__ whh, float* __restrict__ WT) {
    int idx = blockIdx.x*blockDim.x + threadIdx.x;
    if (idx >= 3*DD*DD) return;
    int c = idx / DD, k = idx % DD;
    WT[k*(3*DD) + c] = whh[idx];
}

// ---------------- generic tiled SGEMM:  C[M,N] = A[M,K] @ W[N,K]^T (+bias)(relu) ----
// M must be a multiple of 64, K a multiple of 16 (and 4). N arbitrary.
template<bool BIAS, bool RELU>
__global__ void sgemm_nt(const float* __restrict__ A, const float* __restrict__ W,
                         const float* __restrict__ bias, float* __restrict__ C,
                         int M, int N, int K) {
    const int BM=64, BN=64, BK=16, TM=4, TN=4;
    __shared__ float As[BK][BM+4];
    __shared__ float Ws[BK][BN+4];
    int tid = threadIdx.x;                  // 256 threads
    int m0 = blockIdx.y * BM;
    int n0 = blockIdx.x * BN;
    int tx = tid & 15;                      // n dir (16)
    int ty = tid >> 4;                      // m dir (16)
    int lr = tid >> 2;                      // load row 0..63
    int lc = (tid & 3) * 4;                 // load col {0,4,8,12}

    float acc[TM][TN];
    #pragma unroll
    for (int i=0;i<TM;i++)
        #pragma unroll
        for (int j=0;j<TN;j++) acc[i][j]=0.f;

    for (int k0 = 0; k0 < K; k0 += BK) {
        float4 av = *reinterpret_cast<const float4*>(A + (size_t)(m0+lr)*K + k0 + lc);
        float4 wv = make_float4(0.f,0.f,0.f,0.f);
        if (n0 + lr < N)
            wv = *reinterpret_cast<const float4*>(W + (size_t)(n0+lr)*K + k0 + lc);
        As[lc+0][lr]=av.x; As[lc+1][lr]=av.y; As[lc+2][lr]=av.z; As[lc+3][lr]=av.w;
        Ws[lc+0][lr]=wv.x; Ws[lc+1][lr]=wv.y; Ws[lc+2][lr]=wv.z; Ws[lc+3][lr]=wv.w;
        __syncthreads();
        #pragma unroll
        for (int k=0;k<BK;k++) {
            float a[TM], b[TN];
            #pragma unroll
            for (int i=0;i<TM;i++) a[i] = As[k][ty*TM+i];
            #pragma unroll
            for (int j=0;j<TN;j++) b[j] = Ws[k][tx*TN+j];
            #pragma unroll
            for (int i=0;i<TM;i++)
                #pragma unroll
                for (int j=0;j<TN;j++) acc[i][j] = fmaf(a[i], b[j], acc[i][j]);
        }
        __syncthreads();
    }
    #pragma unroll
    for (int i=0;i<TM;i++) {
        int m = m0 + ty*TM + i;
        #pragma unroll
        for (int j=0;j<TN;j++) {
            int n = n0 + tx*TN + j;
            if (n < N) {
                float v = acc[i][j];
                if (BIAS) v += bias[n];
                if (RELU) v = fmaxf(v, 0.f);
                C[(size_t)m*N + n] = v;
            }
        }
    }
}

// ---------------- GNN rep per batch ----------------
__global__ void gnn_kernel(const int* __restrict__ seq, const float* __restrict__ emb,
                           float* __restrict__ shortu) {
    int b = blockIdx.x;
    int tid = threadIdx.x;              // 128
    __shared__ int s_uq[LL];
    __shared__ int s_nu;
    __shared__ unsigned char s_A[LL][LL];
    __shared__ float s_deg[LL];
    __shared__ float s_e[LL][DD];

    for (int i = tid; i < LL*LL; i += 128) ((unsigned char*)s_A)[i] = 0;
    __syncthreads();

    if (tid == 0) {
        int vals[LL]; int nv = 0;
        for (int l = 0; l < LL; l++) {
            int s = seq[b*LL + l];
            if (s > 0) vals[nv++] = s;
        }
        int srt[LL];
        for (int i = 0; i < nv; i++) srt[i] = vals[i];
        for (int i = 1; i < nv; i++) {          // insertion sort
            int key = srt[i]; int j = i-1;
            while (j >= 0 && srt[j] > key) { srt[j+1] = srt[j]; j--; }
            srt[j+1] = key;
        }
        int nu = 0;
        for (int i = 0; i < nv; i++)
            if (i == 0 || srt[i] != srt[i-1]) s_uq[nu++] = srt[i];
        s_nu = nu;
        if (nu > 1) {
            // uid of first valid
            auto uid_of = [&](int v) {
                int lo = 0, hi = nu-1;
                while (lo < hi) { int mid = (lo+hi) >> 1; if (s_uq[mid] < v) lo = mid+1; else hi = mid; }
                return lo;
            };
            int prev = uid_of(vals[0]);
            for (int j = 1; j < nv; j++) {
                int cur = uid_of(vals[j]);
                s_A[prev][cur] = 1;
                prev = cur;
            }
        }
    }
    __syncthreads();
    int nu = s_nu;
    if (tid < LL) {
        float dg = 0.f;
        for (int j = 0; j < LL; j++) dg += (float)s_A[tid][j];
        s_deg[tid] = dg;
    }
    for (int i = 0; i < nu; i++)
        s_e[i][tid] = emb[(size_t)s_uq[i]*DD + tid];
    __syncthreads();

    float accT = 0.f;
    for (int i = 0; i < nu; i++) {
        float s = 0.f;
        for (int j = 0; j < nu; j++)
            if (s_A[i][j]) s += s_e[j][tid];
        float val = s / (s_deg[i] + 1e-8f);
        float lr = (val > 0.f) ? val : 0.01f*val;
        accT += lr + s_e[i][tid];
    }
    shortu[(size_t)b*DD + tid] = accT / fmaxf((float)nu, 1.0f);
}

// ---------------- fused GRU step ----------------
#define GRU_ROWS 8
__global__ void gru_step_kernel(const float* __restrict__ gi, const float* __restrict__ WT,
                                const float* __restrict__ bhh, float* __restrict__ h,
                                float* __restrict__ hseq, int t) {
    int b0 = blockIdx.x * GRU_ROWS;
    int d = threadIdx.x;                 // 128
    __shared__ float sh[GRU_ROWS][DD];
    #pragma unroll
    for (int r = 0; r < GRU_ROWS; r++) sh[r][d] = h[(size_t)(b0+r)*DD + d];
    __syncthreads();
    float aR[GRU_ROWS], aZ[GRU_ROWS], aN[GRU_ROWS];
    #pragma unroll
    for (int r = 0; r < GRU_ROWS; r++) { aR[r]=0.f; aZ[r]=0.f; aN[r]=0.f; }
    for (int k = 0; k < DD; k++) {
        float w0 = WT[k*384 + d];
        float w1 = WT[k*384 + 128 + d];
        float w2 = WT[k*384 + 256 + d];
        #pragma unroll
        for (int r = 0; r < GRU_ROWS; r++) {
            float hk = sh[r][k];
            aR[r] = fmaf(hk, w0, aR[r]);
            aZ[r] = fmaf(hk, w1, aZ[r]);
            aN[r] = fmaf(hk, w2, aN[r]);
        }
    }
    float bR = bhh[d], bZ = bhh[128+d], bN = bhh[256+d];
    #pragma unroll
    for (int r = 0; r < GRU_ROWS; r++) {
        int b = b0 + r;
        size_t gb = ((size_t)b*LL + t)*384;
        float rr = 1.f/(1.f + expf(-(gi[gb + d]       + aR[r] + bR)));
        float zz = 1.f/(1.f + expf(-(gi[gb + 128 + d] + aZ[r] + bZ)));
        float nn = tanhf(gi[gb + 256 + d] + rr*(aN[r] + bN));
        float hold = sh[r][d];
        float hnew = (1.f - zz)*nn + zz*hold;
        h[(size_t)b*DD + d] = hnew;
        hseq[((size_t)b*LL + t)*DD + d] = hnew;
    }
}

// ---------------- attention (one block per (b,h)) ----------------
__global__ void attn_kernel(const float* __restrict__ qkv, float* __restrict__ attno) {
    int b = blockIdx.x, h = blockIdx.y;
    __shared__ float sq[LL][64];
    __shared__ float sk[LL][65];    // padded: strided j access in score phase
    __shared__ float sv[LL][64];
    __shared__ float S[LL][LL];
    int tid = threadIdx.x;          // 128
    const float* base = qkv + ((size_t)b*LL)*384 + h*64;
    for (int idx = tid; idx < LL*64; idx += 128) {
        int l = idx >> 6, dd = idx & 63;
        sq[l][dd] = base[l*384 + dd];
        sk[l][dd] = base[l*384 + 128 + dd];
        sv[l][dd] = base[l*384 + 256 + dd];
    }
    __syncthreads();
    for (int idx = tid; idx < LL*LL; idx += 128) {
        int i = idx / LL, j = idx % LL;
        float s = 0.f;
        #pragma unroll
        for (int dd = 0; dd < 64; dd++) s = fmaf(sq[i][dd], sk[j][dd], s);
        S[i][j] = s * 0.125f;
    }
    __syncthreads();
    if (tid < LL) {
        float mx = -1e30f;
        for (int j = 0; j < LL; j++) mx = fmaxf(mx, S[tid][j]);
        float sum = 0.f;
        for (int j = 0; j < LL; j++) { float e = expf(S[tid][j]-mx); S[tid][j] = e; sum += e; }
        float inv = 1.f/sum;
        for (int j = 0; j < LL; j++) S[tid][j] *= inv;
    }
    __syncthreads();
    float* obase = attno + ((size_t)b*LL)*DD + h*64;
    for (int idx = tid; idx < LL*64; idx += 128) {
        int i = idx >> 6, dd = idx & 63;
        float s = 0.f;
        for (int j = 0; j < LL; j++) s = fmaf(S[i][j], sv[j][dd], s);
        obase[i*DD + dd] = s;
    }
}

// ---------------- layernorm on (x+y), warp per row ----------------
__global__ void ln_kernel(const float* __restrict__ x, const float* __restrict__ y,
                          const float* __restrict__ g, const float* __restrict__ bta,
                          float* __restrict__ out, int rows) {
    int row = blockIdx.x * 8 + (threadIdx.x >> 5);
    int lane = threadIdx.x & 31;
    if (row >= rows) return;
    const float* px = x + (size_t)row*DD;
    const float* py = y + (size_t)row*DD;
    float v[4]; float s = 0.f;
    #pragma unroll
    for (int i=0;i<4;i++){ v[i] = px[lane+32*i] + py[lane+32*i]; s += v[i]; }
    #pragma unroll
    for (int o=16;o>0;o>>=1) s += __shfl_xor_sync(0xffffffffu, s, o);
    float m = s * (1.f/128.f);
    float vs = 0.f;
    #pragma unroll
    for (int i=0;i<4;i++){ float dv = v[i]-m; vs += dv*dv; }
    #pragma unroll
    for (int o=16;o>0;o>>=1) vs += __shfl_xor_sync(0xffffffffu, vs, o);
    float inv = rsqrtf(vs*(1.f/128.f) + 1e-5f);
    #pragma unroll
    for (int i=0;i<4;i++){
        int c = lane+32*i;
        out[(size_t)row*DD + c] = (v[i]-m)*inv*g[c] + bta[c];
    }
}

// ---------------- pooling + e_hat ----------------
__global__ void pool_kernel(const int* __restrict__ seq, const float* __restrict__ hseq,
                            const float* __restrict__ hattn, const float* __restrict__ shortu,
                            float* __restrict__ ehat) {
    int b = blockIdx.x;
    int d = threadIdx.x;  // 128
    float a1 = 0.f, a2 = 0.f; int cnt = 0;
    for (int l = 0; l < LL; l++) {
        if (seq[b*LL + l] > 0) {
            cnt++;
            a1 += hseq[((size_t)b*LL + l)*DD + d];
            a2 += hattn[((size_t)b*LL + l)*DD + d];
        }
    }
    float len = fmaxf((float)cnt, 1.0f);
    ehat[(size_t)b*DD + d] = shortu[(size_t)b*DD + d] + (a1 + a2) / len;
}

// ---------------- host launcher ----------------
static float* symf(const void* sym) { void* p = nullptr; cudaGetSymbolAddress(&p, sym); return (float*)p; }

extern "C" void kernel_launch(void* const* d_in, const int* in_sizes, int n_in,
                              void* d_out, int out_size) {
    const int*   seq       = (const int*)  d_in[0];
    const float* item_emb  = (const float*)d_in[1];
    const float* pos_emb   = (const float*)d_in[2];
    const float* gru_wih   = (const float*)d_in[3];
    const float* gru_whh   = (const float*)d_in[4];
    const float* gru_bih   = (const float*)d_in[5];
    const float* gru_bhh   = (const float*)d_in[6];
    const float* in_proj_w = (const float*)d_in[7];
    const float* in_proj_b = (const float*)d_in[8];
    const float* out_proj_w= (const float*)d_in[9];
    const float* out_proj_b= (const float*)d_in[10];
    const float* ln1_g     = (const float*)d_in[11];
    const float* ln1_b     = (const float*)d_in[12];
    const float* ln2_g     = (const float*)d_in[13];
    const float* ln2_b     = (const float*)d_in[14];
    const float* ff1_w     = (const float*)d_in[15];
    const float* ff1_b     = (const float*)d_in[16];
    const float* ff2_w     = (const float*)d_in[17];
    const float* ff2_b     = (const float*)d_in[18];
    float* out = (float*)d_out;

    float* px    = symf(g_x);
    float* pgi   = symf(g_gi);
    float* ph    = symf(g_h);
    float* phseq = symf(g_hseq);
    float* phpos = symf(g_hpos);
    float* pqkv  = symf(g_qkv);
    float* pattno= symf(g_attno);
    float* poproj= symf(g_oproj);
    float* ph1   = symf(g_h1);
    float* pff   = symf(g_ff);
    float* pff2  = symf(g_ff2);
    float* phattn= symf(g_hattn);
    float* pshort= symf(g_short);
    float* pehat = symf(g_ehat);
    float* pWT   = symf(g_WT);

    const int totBLD = BLr*DD;

    // 1. embedding gather + mask
    embed_kernel<<<(totBLD+255)/256, 256>>>(seq, item_emb, px);

    // 2. GNN short_u (independent of GRU path)
    gnn_kernel<<<BB, 128>>>(seq, item_emb, pshort);

    // 3. gi = x @ Wih^T + bih   (M=102400, N=384, K=128)
    {
        dim3 grid((384+63)/64, BLr/64);
        sgemm_nt<true,false><<<grid, 256>>>(px, gru_wih, gru_bih, pgi, BLr, 384, DD);
    }

    // 4. transpose Whh, zero h
    transpose_whh<<<(3*DD*DD+255)/256, 256>>>(gru_whh, pWT);
    zero_kernel<<<(BB*DD+255)/256, 256>>>(ph, BB*DD);

    // 5. GRU over time
    for (int t = 0; t < LL; t++)
        gru_step_kernel<<<BB/GRU_ROWS, 128>>>(pgi, pWT, gru_bhh, ph, phseq, t);

    // 6. h = h_seq + pos
    addpos_kernel<<<(totBLD+255)/256, 256>>>(phseq, pos_emb, phpos);

    // 7. qkv = h @ in_proj^T + b
    {
        dim3 grid((384+63)/64, BLr/64);
        sgemm_nt<true,false><<<grid, 256>>>(phpos, in_proj_w, in_proj_b, pqkv, BLr, 384, DD);
    }

    // 8. attention
    {
        dim3 grid(BB, 2);
        attn_kernel<<<grid, 128>>>(pqkv, pattno);
    }

    // 9. out_proj
    {
        dim3 grid((DD+63)/64, BLr/64);
        sgemm_nt<true,false><<<grid, 256>>>(pattno, out_proj_w, out_proj_b, poproj, BLr, DD, DD);
    }

    // 10. ln1(h + o)
    ln_kernel<<<BLr/8, 256>>>(phpos, poproj, ln1_g, ln1_b, ph1, BLr);

    // 11. ff1 (relu)
    {
        dim3 grid((512+63)/64, BLr/64);
        sgemm_nt<true,true><<<grid, 256>>>(ph1, ff1_w, ff1_b, pff, BLr, 512, DD);
    }
    // 12. ff2
    {
        dim3 grid((DD+63)/64, BLr/64);
        sgemm_nt<true,false><<<grid, 256>>>(pff, ff2_w, ff2_b, pff2, BLr, DD, 512);
    }

    // 13. ln2(h1 + ff)
    ln_kernel<<<BLr/8, 256>>>(ph1, pff2, ln2_g, ln2_b, phattn, BLr);

    // 14. pooling + e_hat
    pool_kernel<<<BB, 128>>>(seq, phseq, phattn, pshort, pehat);

    // 15. logits = e_hat @ item_emb^T  (M=2048, N=50001, K=128)
    {
        dim3 grid((VO+63)/64, BB/64);
        sgemm_nt<false,false><<<grid, 256>>>(pehat, item_emb, nullptr, out, BB, VO, DD);
    }
}

// round 3
// speedup vs baseline: 1.1846x; 1.1846x over previous
#include <cuda_runtime.h>
#include <cuda_bf16.h>
#include <math.h>

#define BB 2048
#define LL 50
#define DD 128
#define VO 50001
#define BLr (BB*LL)          // 102400 rows

typedef unsigned long long ULL;

// ---------------- f32x2 helpers (sm_100+ packed fp32 FMA) ----------------
__device__ __forceinline__ ULL pk2(float lo, float hi) {
    ULL r; asm("mov.b64 %0,{%1,%2};" : "=l"(r) : "f"(lo), "f"(hi)); return r;
}
__device__ __forceinline__ void fma2(ULL& d, ULL a, ULL b) {
    asm("fma.rn.f32x2 %0,%1,%2,%0;" : "+l"(d) : "l"(a), "l"(b));
}
__device__ __forceinline__ float2 upk2(ULL v) {
    float2 r; asm("mov.b64 {%0,%1},%2;" : "=f"(r.x), "=f"(r.y) : "l"(v)); return r;
}

// ---------------- scratch (device globals; no allocation allowed) -------------
__device__ float g_x[(size_t)BLr*DD];        // emb[seq]*mask
__device__ float g_gi[(size_t)BLr*3*DD];     // GRU input gates (precomputed)
__device__ float g_hseq[(size_t)BLr*DD];     // GRU outputs
__device__ float g_hpos[(size_t)BLr*DD];     // hseq + pos
__device__ float g_qkv[(size_t)BLr*3*DD];
__device__ float g_attno[(size_t)BLr*DD];    // attention out (pre out_proj)
__device__ float g_oproj[(size_t)BLr*DD];    // out_proj result
__device__ float g_h1[(size_t)BLr*DD];
__device__ float g_ff[(size_t)BLr*4*DD];
__device__ float g_ff2[(size_t)BLr*DD];
__device__ float g_hattn[(size_t)BLr*DD];
__device__ float g_short[(size_t)BB*DD];
__device__ float g_ehat[(size_t)BB*DD];
__device__ float g_WT[(size_t)DD*3*DD];      // Whh transposed: WT[k][c], c in [0,384)

// ---------------- small elementwise kernels ----------------
__global__ void embed_kernel(const int* __restrict__ seq, const float* __restrict__ emb,
                             float* __restrict__ x) {
    int idx = blockIdx.x*blockDim.x + threadIdx.x;
    if (idx >= BLr*DD) return;
    int bl = idx >> 7; int d = idx & 127;
    int s = seq[bl];
    x[idx] = (s > 0) ? emb[(size_t)s*DD + d] : 0.f;
}

__global__ void transpose_whh(const float* __restrict__ whh, float* __restrict__ WT) {
    int idx = blockIdx.x*blockDim.x + threadIdx.x;
    if (idx >= 3*DD*DD) return;
    int c = idx / DD, k = idx % DD;
    WT[k*(3*DD) + c] = whh[idx];
}

// ---------------- f32x2 tiled SGEMM:  C[M,N] = A[M,K] @ W[N,K]^T (+bias)(relu) ----
// 128x128x16 tiles, double-buffered, 256 threads, 8x8 micro (packed pairs along N).
// M % 128 == 0, K % 16 == 0. N arbitrary.
template<bool BIAS, bool RELU>
__global__ void __launch_bounds__(256, 2)
sgemm128(const float* __restrict__ A, const float* __restrict__ W,
         const float* __restrict__ bias, float* __restrict__ C,
         int M, int N, int K) {
    __shared__ __align__(16) float As[2][16][132];
    __shared__ __align__(16) float Bs[2][16][132];
    const int tid = threadIdx.x;
    const int m0 = blockIdx.y * 128;
    const int n0 = blockIdx.x * 128;
    const int tx = tid & 15;          // n-dir
    const int ty = tid >> 4;          // m-dir
    const int lrow = tid >> 2;        // 0..63
    const int lcol = (tid & 3) * 4;   // {0,4,8,12}

    ULL accA[8][2], accB[8][2];
    #pragma unroll
    for (int i = 0; i < 8; i++) {
        accA[i][0]=0ull; accA[i][1]=0ull; accB[i][0]=0ull; accB[i][1]=0ull;
    }

    float4 ra[2], rw[2];
    const int nt = K >> 4;

    // prologue: load tile 0
    #pragma unroll
    for (int j = 0; j < 2; j++) {
        int row = lrow + j*64;
        ra[j] = *reinterpret_cast<const float4*>(A + (size_t)(m0+row)*K + lcol);
        int wr = n0 + row;
        rw[j] = (wr < N) ? *reinterpret_cast<const float4*>(W + (size_t)wr*K + lcol)
                         : make_float4(0.f,0.f,0.f,0.f);
    }
    #pragma unroll
    for (int j = 0; j < 2; j++) {
        int row = lrow + j*64;
        As[0][lcol+0][row]=ra[j].x; As[0][lcol+1][row]=ra[j].y;
        As[0][lcol+2][row]=ra[j].z; As[0][lcol+3][row]=ra[j].w;
        Bs[0][lcol+0][row]=rw[j].x; Bs[0][lcol+1][row]=rw[j].y;
        Bs[0][lcol+2][row]=rw[j].z; Bs[0][lcol+3][row]=rw[j].w;
    }
    __syncthreads();

    int buf = 0;
    for (int t = 0; t < nt; t++) {
        if (t + 1 < nt) {
            int k0 = (t+1) << 4;
            #pragma unroll
            for (int j = 0; j < 2; j++) {
                int row = lrow + j*64;
                ra[j] = *reinterpret_cast<const float4*>(A + (size_t)(m0+row)*K + k0 + lcol);
                int wr = n0 + row;
                rw[j] = (wr < N) ? *reinterpret_cast<const float4*>(W + (size_t)wr*K + k0 + lcol)
                                 : make_float4(0.f,0.f,0.f,0.f);
            }
        }
        // compute on buf
        #pragma unroll
        for (int k = 0; k < 16; k++) {
            float4 a0 = *reinterpret_cast<const float4*>(&As[buf][k][ty*8]);
            float4 a1 = *reinterpret_cast<const float4*>(&As[buf][k][ty*8+4]);
            ulonglong2 bv0 = *reinterpret_cast<const ulonglong2*>(&Bs[buf][k][tx*4]);
            ulonglong2 bv1 = *reinterpret_cast<const ulonglong2*>(&Bs[buf][k][64 + tx*4]);
            float av[8] = {a0.x,a0.y,a0.z,a0.w,a1.x,a1.y,a1.z,a1.w};
            #pragma unroll
            for (int i = 0; i < 8; i++) {
                ULL ad = pk2(av[i], av[i]);
                fma2(accA[i][0], ad, bv0.x);
                fma2(accA[i][1], ad, bv0.y);
                fma2(accB[i][0], ad, bv1.x);
                fma2(accB[i][1], ad, bv1.y);
            }
        }
        if (t + 1 < nt) {
            int nb = buf ^ 1;
            #pragma unroll
            for (int j = 0; j < 2; j++) {
                int row = lrow + j*64;
                As[nb][lcol+0][row]=ra[j].x; As[nb][lcol+1][row]=ra[j].y;
                As[nb][lcol+2][row]=ra[j].z; As[nb][lcol+3][row]=ra[j].w;
                Bs[nb][lcol+0][row]=rw[j].x; Bs[nb][lcol+1][row]=rw[j].y;
                Bs[nb][lcol+2][row]=rw[j].z; Bs[nb][lcol+3][row]=rw[j].w;
            }
            __syncthreads();
            buf = nb;
        }
    }

    // epilogue
    const int nA = n0 + tx*4;
    const int nB = nA + 64;
    float4 bA = make_float4(0.f,0.f,0.f,0.f), bB = bA;
    if (BIAS) {
        if (nA + 3 < N) bA = *reinterpret_cast<const float4*>(bias + nA);
        else { float t4[4]={0,0,0,0}; for (int q=0;q<4;q++) if (nA+q<N) t4[q]=bias[nA+q];
               bA = make_float4(t4[0],t4[1],t4[2],t4[3]); }
        if (nB + 3 < N) bB = *reinterpret_cast<const float4*>(bias + nB);
        else { float t4[4]={0,0,0,0}; for (int q=0;q<4;q++) if (nB+q<N) t4[q]=bias[nB+q];
               bB = make_float4(t4[0],t4[1],t4[2],t4[3]); }
    }
    const bool vec_ok = ((N & 3) == 0);
    #pragma unroll
    for (int i = 0; i < 8; i++) {
        int m = m0 + ty*8 + i;
        float* crow = C + (size_t)m*N;
        float2 x0 = upk2(accA[i][0]), x1 = upk2(accA[i][1]);
        float4 v = make_float4(x0.x + bA.x, x0.y + bA.y, x1.x + bA.z, x1.y + bA.w);
        if (RELU) { v.x=fmaxf(v.x,0.f); v.y=fmaxf(v.y,0.f); v.z=fmaxf(v.z,0.f); v.w=fmaxf(v.w,0.f); }
        if (vec_ok && nA + 3 < N) *reinterpret_cast<float4*>(crow + nA) = v;
        else {
            if (nA+0 < N) crow[nA+0]=v.x; if (nA+1 < N) crow[nA+1]=v.y;
            if (nA+2 < N) crow[nA+2]=v.z; if (nA+3 < N) crow[nA+3]=v.w;
        }
        float2 y0 = upk2(accB[i][0]), y1 = upk2(accB[i][1]);
        float4 w4 = make_float4(y0.x + bB.x, y0.y + bB.y, y1.x + bB.z, y1.y + bB.w);
        if (RELU) { w4.x=fmaxf(w4.x,0.f); w4.y=fmaxf(w4.y,0.f); w4.z=fmaxf(w4.z,0.f); w4.w=fmaxf(w4.w,0.f); }
        if (vec_ok && nB + 3 < N) *reinterpret_cast<float4*>(crow + nB) = w4;
        else {
            if (nB+0 < N) crow[nB+0]=w4.x; if (nB+1 < N) crow[nB+1]=w4.y;
            if (nB+2 < N) crow[nB+2]=w4.z; if (nB+3 < N) crow[nB+3]=w4.w;
        }
    }
}

// ---------------- GNN rep per batch ----------------
__global__ void gnn_kernel(const int* __restrict__ seq, const float* __restrict__ emb,
                           float* __restrict__ shortu) {
    int b = blockIdx.x;
    int tid = threadIdx.x;              // 128
    __shared__ int s_uq[LL];
    __shared__ int s_nu;
    __shared__ unsigned char s_A[LL][LL];
    __shared__ float s_deg[LL];
    __shared__ float s_e[LL][DD];

    for (int i = tid; i < LL*LL; i += 128) ((unsigned char*)s_A)[i] = 0;
    __syncthreads();

    if (tid == 0) {
        int vals[LL]; int nv = 0;
        for (int l = 0; l < LL; l++) {
            int s = seq[b*LL + l];
            if (s > 0) vals[nv++] = s;
        }
        int srt[LL];
        for (int i = 0; i < nv; i++) srt[i] = vals[i];
        for (int i = 1; i < nv; i++) {          // insertion sort
            int key = srt[i]; int j = i-1;
            while (j >= 0 && srt[j] > key) { srt[j+1] = srt[j]; j--; }
            srt[j+1] = key;
        }
        int nu = 0;
        for (int i = 0; i < nv; i++)
            if (i == 0 || srt[i] != srt[i-1]) s_uq[nu++] = srt[i];
        s_nu = nu;
        if (nu > 1) {
            auto uid_of = [&](int v) {
                int lo = 0, hi = nu-1;
                while (lo < hi) { int mid = (lo+hi) >> 1; if (s_uq[mid] < v) lo = mid+1; else hi = mid; }
                return lo;
            };
            int prev = uid_of(vals[0]);
            for (int j = 1; j < nv; j++) {
                int cur = uid_of(vals[j]);
                s_A[prev][cur] = 1;
                prev = cur;
            }
        }
    }
    __syncthreads();
    int nu = s_nu;
    if (tid < LL) {
        float dg = 0.f;
        for (int j = 0; j < LL; j++) dg += (float)s_A[tid][j];
        s_deg[tid] = dg;
    }
    for (int i = 0; i < nu; i++)
        s_e[i][tid] = emb[(size_t)s_uq[i]*DD + tid];
    __syncthreads();

    float accT = 0.f;
    for (int i = 0; i < nu; i++) {
        float s = 0.f;
        for (int j = 0; j < nu; j++)
            if (s_A[i][j]) s += s_e[j][tid];
        float val = s / (s_deg[i] + 1e-8f);
        float lr = (val > 0.f) ? val : 0.01f*val;
        accT += lr + s_e[i][tid];
    }
    shortu[(size_t)b*DD + tid] = accT / fmaxf((float)nu, 1.0f);
}

// ---------------- GRU: all 50 steps in one kernel (rows independent across blocks) --
// 16 batch rows per block (8 f32x2 pairs), Whh^T cached in dynamic smem (192KB).
#define GRU_ROWS 16
#define GRU_PAIRS 8
#define GRU_SMEM (3*DD*DD*4 + DD*GRU_PAIRS*8)

__device__ __forceinline__ float sigmf(float x) { return 1.f / (1.f + __expf(-x)); }
__device__ __forceinline__ float tanhfast(float x) {
    float e = __expf(-2.f * x);
    return (1.f - e) / (1.f + e);
}

__global__ void gru_all_kernel(const float* __restrict__ gi, const float* __restrict__ WT,
                               const float* __restrict__ bhh, const float* __restrict__ pos,
                               float* __restrict__ hseq, float* __restrict__ hpos) {
    extern __shared__ float sm[];
    float* sW = sm;                                   // 3*DD*DD floats = 49152
    float2* shp = (float2*)(sm + 3*DD*DD);            // [DD][GRU_PAIRS]
    const int d = threadIdx.x;                        // 128
    const int b0 = blockIdx.x * GRU_ROWS;

    // load Whh^T into shared (coalesced float4)
    for (int i = d; i < (3*DD*DD)/4; i += DD)
        reinterpret_cast<float4*>(sW)[i] = reinterpret_cast<const float4*>(WT)[i];
    #pragma unroll
    for (int p = 0; p < GRU_PAIRS; p++) shp[d*GRU_PAIRS + p] = make_float2(0.f, 0.f);
    __syncthreads();

    const float bR = bhh[d], bZ = bhh[DD+d], bN = bhh[2*DD+d];

    for (int t = 0; t < LL; t++) {
        ULL aR[GRU_PAIRS], aZ[GRU_PAIRS], aN[GRU_PAIRS];
        #pragma unroll
        for (int p = 0; p < GRU_PAIRS; p++) { aR[p]=0ull; aZ[p]=0ull; aN[p]=0ull; }

        #pragma unroll 4
        for (int k = 0; k < DD; k++) {
            float w0 = sW[k*384 + d];
            float w1 = sW[k*384 + 128 + d];
            float w2 = sW[k*384 + 256 + d];
            ULL d0 = pk2(w0, w0), d1 = pk2(w1, w1), d2 = pk2(w2, w2);
            #pragma unroll
            for (int p = 0; p < GRU_PAIRS; p++) {
                ULL hk = *reinterpret_cast<const ULL*>(&shp[k*GRU_PAIRS + p]);
                fma2(aR[p], hk, d0);
                fma2(aZ[p], hk, d1);
                fma2(aN[p], hk, d2);
            }
        }

        float posv = pos[t*DD + d];
        float hnew[GRU_ROWS];
        #pragma unroll
        for (int p = 0; p < GRU_PAIRS; p++) {
            float2 fR = upk2(aR[p]), fZ = upk2(aZ[p]), fN = upk2(aN[p]);
            float2 hold2 = shp[d*GRU_PAIRS + p];
            #pragma unroll
            for (int l = 0; l < 2; l++) {
                int r = 2*p + l;
                int b = b0 + r;
                size_t gb = ((size_t)b*LL + t)*384;
                float hr = l ? fR.y : fR.x;
                float hz = l ? fZ.y : fZ.x;
                float hn = l ? fN.y : fN.x;
                float rr = sigmf(gi[gb + d] + hr + bR);
                float zz = sigmf(gi[gb + 128 + d] + hz + bZ);
                float nn = tanhfast(gi[gb + 256 + d] + rr*(hn + bN));
                float hold = l ? hold2.y : hold2.x;
                float hv = (1.f - zz)*nn + zz*hold;
                hnew[r] = hv;
                size_t o = ((size_t)b*LL + t)*DD + d;
                hseq[o] = hv;
                hpos[o] = hv + posv;
            }
        }
        __syncthreads();
        #pragma unroll
        for (int p = 0; p < GRU_PAIRS; p++)
            shp[d*GRU_PAIRS + p] = make_float2(hnew[2*p], hnew[2*p+1]);
        __syncthreads();
    }
}

// ---------------- attention (one block per (b,h)) ----------------
__global__ void attn_kernel(const float* __restrict__ qkv, float* __restrict__ attno) {
    int b = blockIdx.x, h = blockIdx.y;
    __shared__ float sq[LL][64];
    __shared__ float sk[LL][65];
    __shared__ float sv[LL][64];
    __shared__ float S[LL][LL];
    int tid = threadIdx.x;          // 128
    const float* base = qkv + ((size_t)b*LL)*384 + h*64;
    for (int idx = tid; idx < LL*64; idx += 128) {
        int l = idx >> 6, dd = idx & 63;
        sq[l][dd] = base[l*384 + dd];
        sk[l][dd] = base[l*384 + 128 + dd];
        sv[l][dd] = base[l*384 + 256 + dd];
    }
    __syncthreads();
    for (int idx = tid; idx < LL*LL; idx += 128) {
        int i = idx / LL, j = idx % LL;
        float s = 0.f;
        #pragma unroll
        for (int dd = 0; dd < 64; dd++) s = fmaf(sq[i][dd], sk[j][dd], s);
        S[i][j] = s * 0.125f;
    }
    __syncthreads();
    if (tid < LL) {
        float mx = -1e30f;
        for (int j = 0; j < LL; j++) mx = fmaxf(mx, S[tid][j]);
        float sum = 0.f;
        for (int j = 0; j < LL; j++) { float e = __expf(S[tid][j]-mx); S[tid][j] = e; sum += e; }
        float inv = 1.f/sum;
        for (int j = 0; j < LL; j++) S[tid][j] *= inv;
    }
    __syncthreads();
    float* obase = attno + ((size_t)b*LL)*DD + h*64;
    for (int idx = tid; idx < LL*64; idx += 128) {
        int i = idx >> 6, dd = idx & 63;
        float s = 0.f;
        for (int j = 0; j < LL; j++) s = fmaf(S[i][j], sv[j][dd], s);
        obase[i*DD + dd] = s;
    }
}

// ---------------- layernorm on (x+y), warp per row ----------------
__global__ void ln_kernel(const float* __restrict__ x, const float* __restrict__ y,
                          const float* __restrict__ g, const float* __restrict__ bta,
                          float* __restrict__ out, int rows) {
    int row = blockIdx.x * 8 + (threadIdx.x >> 5);
    int lane = threadIdx.x & 31;
    if (row >= rows) return;
    const float* px = x + (size_t)row*DD;
    const float* py = y + (size_t)row*DD;
    float v[4]; float s = 0.f;
    #pragma unroll
    for (int i=0;i<4;i++){ v[i] = px[lane+32*i] + py[lane+32*i]; s += v[i]; }
    #pragma unroll
    for (int o=16;o>0;o>>=1) s += __shfl_xor_sync(0xffffffffu, s, o);
    float m = s * (1.f/128.f);
    float vs = 0.f;
    #pragma unroll
    for (int i=0;i<4;i++){ float dv = v[i]-m; vs += dv*dv; }
    #pragma unroll
    for (int o=16;o>0;o>>=1) vs += __shfl_xor_sync(0xffffffffu, vs, o);
    float inv = rsqrtf(vs*(1.f/128.f) + 1e-5f);
    #pragma unroll
    for (int i=0;i<4;i++){
        int c = lane+32*i;
        out[(size_t)row*DD + c] = (v[i]-m)*inv*g[c] + bta[c];
    }
}

// ---------------- pooling + e_hat ----------------
__global__ void pool_kernel(const int* __restrict__ seq, const float* __restrict__ hseq,
                            const float* __restrict__ hattn, const float* __restrict__ shortu,
                            float* __restrict__ ehat) {
    int b = blockIdx.x;
    int d = threadIdx.x;  // 128
    float a1 = 0.f, a2 = 0.f; int cnt = 0;
    for (int l = 0; l < LL; l++) {
        if (seq[b*LL + l] > 0) {
            cnt++;
            a1 += hseq[((size_t)b*LL + l)*DD + d];
            a2 += hattn[((size_t)b*LL + l)*DD + d];
        }
    }
    float len = fmaxf((float)cnt, 1.0f);
    ehat[(size_t)b*DD + d] = shortu[(size_t)b*DD + d] + (a1 + a2) / len;
}

// ---------------- host launcher ----------------
static float* symf(const void* sym) { void* p = nullptr; cudaGetSymbolAddress(&p, sym); return (float*)p; }

extern "C" void kernel_launch(void* const* d_in, const int* in_sizes, int n_in,
                              void* d_out, int out_size) {
    const int*   seq       = (const int*)  d_in[0];
    const float* item_emb  = (const float*)d_in[1];
    const float* pos_emb   = (const float*)d_in[2];
    const float* gru_wih   = (const float*)d_in[3];
    const float* gru_whh   = (const float*)d_in[4];
    const float* gru_bih   = (const float*)d_in[5];
    const float* gru_bhh   = (const float*)d_in[6];
    const float* in_proj_w = (const float*)d_in[7];
    const float* in_proj_b = (const float*)d_in[8];
    const float* out_proj_w= (const float*)d_in[9];
    const float* out_proj_b= (const float*)d_in[10];
    const float* ln1_g     = (const float*)d_in[11];
    const float* ln1_b     = (const float*)d_in[12];
    const float* ln2_g     = (const float*)d_in[13];
    const float* ln2_b     = (const float*)d_in[14];
    const float* ff1_w     = (const float*)d_in[15];
    const float* ff1_b     = (const float*)d_in[16];
    const float* ff2_w     = (const float*)d_in[17];
    const float* ff2_b     = (const float*)d_in[18];
    float* out = (float*)d_out;

    float* px    = symf(g_x);
    float* pgi   = symf(g_gi);
    float* phseq = symf(g_hseq);
    float* phpos = symf(g_hpos);
    float* pqkv  = symf(g_qkv);
    float* pattno= symf(g_attno);
    float* poproj= symf(g_oproj);
    float* ph1   = symf(g_h1);
    float* pff   = symf(g_ff);
    float* pff2  = symf(g_ff2);
    float* phattn= symf(g_hattn);
    float* pshort= symf(g_short);
    float* pehat = symf(g_ehat);
    float* pWT   = symf(g_WT);

    cudaFuncSetAttribute(gru_all_kernel, cudaFuncAttributeMaxDynamicSharedMemorySize, GRU_SMEM);

    const int totBLD = BLr*DD;

    // 1. transpose Whh (first so launch #6 is the qkv GEMM for ncu -s 5)
    transpose_whh<<<(3*DD*DD+255)/256, 256>>>(gru_whh, pWT);

    // 2. embedding gather + mask
    embed_kernel<<<(totBLD+255)/256, 256>>>(seq, item_emb, px);

    // 3. GNN short_u
    gnn_kernel<<<BB, 128>>>(seq, item_emb, pshort);

    // 4. gi = x @ Wih^T + bih   (M=102400, N=384, K=128)
    {
        dim3 grid(384/128, BLr/128);
        sgemm128<true,false><<<grid, 256>>>(px, gru_wih, gru_bih, pgi, BLr, 384, DD);
    }

    // 5. GRU: all 50 steps in one kernel; also writes hpos = hseq + pos
    gru_all_kernel<<<BB/GRU_ROWS, DD, GRU_SMEM>>>(pgi, pWT, gru_bhh, pos_emb, phseq, phpos);

    // 6. qkv = hpos @ in_proj^T + b
    {
        dim3 grid(384/128, BLr/128);
        sgemm128<true,false><<<grid, 256>>>(phpos, in_proj_w, in_proj_b, pqkv, BLr, 384, DD);
    }

    // 7. attention
    {
        dim3 grid(BB, 2);
        attn_kernel<<<grid, 128>>>(pqkv, pattno);
    }

    // 8. out_proj
    {
        dim3 grid(1, BLr/128);
        sgemm128<true,false><<<grid, 256>>>(pattno, out_proj_w, out_proj_b, poproj, BLr, DD, DD);
    }

    // 9. ln1(hpos + o)
    ln_kernel<<<BLr/8, 256>>>(phpos, poproj, ln1_g, ln1_b, ph1, BLr);

    // 10. ff1 (relu)
    {
        dim3 grid(512/128, BLr/128);
        sgemm128<true,true><<<grid, 256>>>(ph1, ff1_w, ff1_b, pff, BLr, 512, DD);
    }
    // 11. ff2
    {
        dim3 grid(1, BLr/128);
        sgemm128<true,false><<<grid, 256>>>(pff, ff2_w, ff2_b, pff2, BLr, DD, 512);
    }

    // 12. ln2(h1 + ff)
    ln_kernel<<<BLr/8, 256>>>(ph1, pff2, ln2_g, ln2_b, phattn, BLr);

    // 13. pooling + e_hat
    pool_kernel<<<BB, 128>>>(seq, phseq, phattn, pshort, pehat);

    // 14. logits = e_hat @ item_emb^T  (M=2048, N=50001, K=128)
    {
        dim3 grid((VO+127)/128, BB/128);
        sgemm128<false,false><<<grid, 256>>>(pehat, item_emb, nullptr, out, BB, VO, DD);
    }
}